// round 13
// baseline (speedup 1.0000x reference)
#include <cuda_runtime.h>
#include <cuda_fp16.h>
#include <cstdint>

namespace {
constexpr int  Bn = 8;
constexpr long Tn = 262144;
constexpr long Sn = 131072;   // output positions
constexpr int  En = 128;      // conv channels = GEMM K
constexpr int  Pn = 64;       // out features  = GEMM N
constexpr int  S_TILE = 128;  // GEMM M per CTA
constexpr int  THREADS = 256;
constexpr int  LDA = 136;     // halves/row, padded -> conflict-free ldmatrix

constexpr int SMEM_TOTAL = S_TILE * LDA * 2;   // 34816 B -> 4 CTAs/SM
}

// B fragments, lane-contiguous: [G(2)][chunk(8)][pair(2)][lane(32)] of uint4
__device__ uint4 g_bfrag[2 * 8 * 2 * 32];
// packed conv taps: [slot(3)][lane(32)] of uint4 (12 half2 per lane)
__device__ uint4 g_cpack[3 * 32];

__device__ __forceinline__ uint32_t smem_u32(const void* p) {
    return (uint32_t)__cvta_generic_to_shared(p);
}
__device__ __forceinline__ __half2 u2h(uint32_t u) {
    return *reinterpret_cast<const __half2*>(&u);
}

#define LDSM_X4(r0, r1, r2, r3, addr)                                            \
    asm volatile("ldmatrix.sync.aligned.m8n8.x4.shared.b16 {%0,%1,%2,%3}, [%4];" \
                 : "=r"(r0), "=r"(r1), "=r"(r2), "=r"(r3) : "r"(addr))

#define MMA16816(d, a0, a1, a2, a3, b0, b1)                                      \
    asm volatile("mma.sync.aligned.m16n8k16.row.col.f32.f16.f16.f32 "            \
                 "{%0,%1,%2,%3},{%4,%5,%6,%7},{%8,%9},{%0,%1,%2,%3};"            \
                 : "+f"((d)[0]), "+f"((d)[1]), "+f"((d)[2]), "+f"((d)[3])        \
                 : "r"(a0), "r"(a1), "r"(a2), "r"(a3), "r"(b0), "r"(b1))

// ---- init 1: pack lin_w (fp32 [64,128]) into fp16 B fragments ----
__global__ void pack_w_kernel(const float* __restrict__ lin_w) {
    const int idx = blockIdx.x * blockDim.x + threadIdx.x;   // 512 threads
    if (idx >= 2 * 8 * 32) return;
    const int lane  = idx & 31;
    const int chunk = (idx >> 5) & 7;
    const int G     = idx >> 8;

    uint32_t r[8];
#pragma unroll
    for (int s = 0; s < 2; s++) {
#pragma unroll
        for (int q = 0; q < 4; q++) {
            const int nt = 2 * s + (q >> 1);
            const int n  = 32 * G + (lane >> 3) * 8 + nt * 2 + ((lane >> 2) & 1);
            const int k  = 16 * chunk + ((q & 1) << 3) + ((lane & 3) << 1);
            const float2 w = *reinterpret_cast<const float2*>(lin_w + n * En + k);
            __half2 h = __halves2half2(__float2half_rn(w.x), __float2half_rn(w.y));
            r[s * 4 + q] = *reinterpret_cast<const uint32_t*>(&h);
        }
    }
    g_bfrag[((G * 8 + chunk) * 2 + 0) * 32 + lane] = make_uint4(r[0], r[1], r[2], r[3]);
    g_bfrag[((G * 8 + chunk) * 2 + 1) * 32 + lane] = make_uint4(r[4], r[5], r[6], r[7]);
}

// ---- init 2: pack conv taps/bias into per-lane half2 layout ----
__global__ void pack_c_kernel(const float* __restrict__ conv_w,
                              const float* __restrict__ conv_b) {
    const int lane = threadIdx.x;   // 32 threads
    if (lane >= 32) return;
    const int c0 = 4 * lane;
    const float4* cw4 = reinterpret_cast<const float4*>(conv_w + 5 * c0);
    float4 q0 = cw4[0], q1 = cw4[1], q2 = cw4[2], q3 = cw4[3], q4 = cw4[4];
    float4 bbv = *reinterpret_cast<const float4*>(conv_b + c0);

    __half2 h[12];
    h[0]  = __floats2half2_rn(q0.x, q1.y);  // wA0
    h[1]  = __floats2half2_rn(q0.y, q1.z);  // wA1
    h[2]  = __floats2half2_rn(q0.z, q1.w);  // wA2
    h[3]  = __floats2half2_rn(q0.w, q2.x);  // wA3
    h[4]  = __floats2half2_rn(q1.x, q2.y);  // wA4
    h[5]  = __floats2half2_rn(q2.z, q3.w);  // wB0
    h[6]  = __floats2half2_rn(q2.w, q4.x);  // wB1
    h[7]  = __floats2half2_rn(q3.x, q4.y);  // wB2
    h[8]  = __floats2half2_rn(q3.y, q4.z);  // wB3
    h[9]  = __floats2half2_rn(q3.z, q4.w);  // wB4
    h[10] = __floats2half2_rn(bbv.x, bbv.y);  // cbA
    h[11] = __floats2half2_rn(bbv.z, bbv.w);  // cbB
    const uint32_t* u = reinterpret_cast<const uint32_t*>(h);
    g_cpack[0 * 32 + lane] = make_uint4(u[0], u[1], u[2],  u[3]);
    g_cpack[1 * 32 + lane] = make_uint4(u[4], u[5], u[6],  u[7]);
    g_cpack[2 * 32 + lane] = make_uint4(u[8], u[9], u[10], u[11]);
}

__global__ void __launch_bounds__(THREADS, 4)
encoder_kernel(const float* __restrict__ x,       // [B, T]
               const float* __restrict__ lin_b,   // [64]
               float* __restrict__ out)           // [B, S, 64]
{
    extern __shared__ char smem[];
    __half* fhi = (__half*)smem;

    const int tid  = threadIdx.x;
    const int wid  = tid >> 5;
    const int lane = tid & 31;
    const int b    = blockIdx.y;
    const long s0  = (long)blockIdx.x * S_TILE;
    const int q    = wid & 3;        // pipeline pair {q, q+4}
    const int G    = wid >> 2;       // n-group

    // ---- conv taps: 3 coalesced LDG.128 of pre-packed half2 ----
    const int c0 = 4 * lane;
    const int pb = 32 * q + 16 * G;              // this warp's 16 A rows
    __half2 wA[5], wB[5], cbA, cbB;
    {
        const uint4 v0 = __ldg(g_cpack + lane);
        const uint4 v1 = __ldg(g_cpack + 32 + lane);
        const uint4 v2 = __ldg(g_cpack + 64 + lane);
        wA[0]=u2h(v0.x); wA[1]=u2h(v0.y); wA[2]=u2h(v0.z); wA[3]=u2h(v0.w);
        wA[4]=u2h(v1.x); wB[0]=u2h(v1.y); wB[1]=u2h(v1.z); wB[2]=u2h(v1.w);
        wB[3]=u2h(v2.x); wB[4]=u2h(v2.y); cbA =u2h(v2.z); cbB =u2h(v2.w);
    }

    // ---- warp-private input window in registers (35 floats across lanes) ----
    const long t0w = 2L * (s0 + pb) - 2;
    float xv0, xv1;
    {
        const float* xb = x + (long)b * Tn;
        long t = t0w + lane;
        xv0 = (t >= 0 && t < Tn) ? xb[t] : 0.f;
        t += 32;
        xv1 = (t >= 0 && t < Tn) ? xb[t] : 0.f;
    }

    // ---- conv1d + ReLU in half2 -> A rows pb..pb+15 ----
    {
        const unsigned m = 0xFFFFFFFFu;
        const __half2 hzero = __float2half2_rn(0.f);
        __half2 X0 = __float2half2_rn(__shfl_sync(m, xv0, 0));
        __half2 X1 = __float2half2_rn(__shfl_sync(m, xv0, 1));
        __half2 X2 = __float2half2_rn(__shfl_sync(m, xv0, 2));
        __half2 X3 = __float2half2_rn(__shfl_sync(m, xv0, 3));
        __half2 X4 = __float2half2_rn(__shfl_sync(m, xv0, 4));
#pragma unroll
        for (int p = 0; p < 16; p++) {
            __half2 vA = __hfma2(wA[0], X0, cbA);
            vA = __hfma2(wA[1], X1, vA);
            vA = __hfma2(wA[2], X2, vA);
            vA = __hfma2(wA[3], X3, vA);
            vA = __hfma2(wA[4], X4, vA);
            vA = __hmax2(vA, hzero);
            __half2 vB = __hfma2(wB[0], X0, cbB);
            vB = __hfma2(wB[1], X1, vB);
            vB = __hfma2(wB[2], X2, vB);
            vB = __hfma2(wB[3], X3, vB);
            vB = __hfma2(wB[4], X4, vB);
            vB = __hmax2(vB, hzero);
            uint2 vh;
            vh.x = *reinterpret_cast<const uint32_t*>(&vA);
            vh.y = *reinterpret_cast<const uint32_t*>(&vB);
            *reinterpret_cast<uint2*>(fhi + (pb + p) * LDA + c0) = vh;
            if (p < 15) {
                X0 = X2; X1 = X3; X2 = X4;
                const int i5 = 2 * p + 5, i6 = 2 * p + 6;   // compile-time consts
                float f3 = (i5 < 32) ? __shfl_sync(m, xv0, i5) : __shfl_sync(m, xv1, i5 - 32);
                float f4 = (i6 < 32) ? __shfl_sync(m, xv0, i6) : __shfl_sync(m, xv1, i6 - 32);
                X3 = __float2half2_rn(f3);
                X4 = __float2half2_rn(f4);
            }
        }
    }

    // ---- pre-barrier: zero acc + prefetch B chunk 0 (smem-independent) ----
    float acc[2][4][4];
#pragma unroll
    for (int mt = 0; mt < 2; mt++)
#pragma unroll
        for (int nt = 0; nt < 4; nt++)
#pragma unroll
            for (int qq = 0; qq < 4; qq++) acc[mt][nt][qq] = 0.f;

    const uint4* bp = g_bfrag + (G * 8) * 2 * 32 + lane;
    uint4 pv0 = __ldg(bp);
    uint4 pv1 = __ldg(bp + 32);

    // pairwise producer/consumer barrier: warps {q, q+4} (drains STS)
    asm volatile("bar.sync %0, 64;" :: "r"(q) : "memory");

    // ---- GEMM: warp tile m32 x n32 on rows 32q..32q+31 ----
    const int aoff0 = (32 * q + (lane & 15)) * LDA + ((lane >> 4) << 3);
    const uint32_t a_s0 = smem_u32(fhi + aoff0);
    const uint32_t a_s1 = smem_u32(fhi + aoff0 + 16 * LDA);

#pragma unroll
    for (int c = 0; c < 8; c++) {
        const uint32_t kB = c * 32;
        uint32_t ah[2][4];
        LDSM_X4(ah[0][0], ah[0][1], ah[0][2], ah[0][3], a_s0 + kB);
        LDSM_X4(ah[1][0], ah[1][1], ah[1][2], ah[1][3], a_s1 + kB);
        const uint4 v0 = pv0;
        const uint4 v1 = pv1;
        if (c < 7) {                        // prefetch next chunk's B
            pv0 = __ldg(bp + (c + 1) * 64);
            pv1 = __ldg(bp + (c + 1) * 64 + 32);
        }
        const uint32_t bh[2][4] = {{v0.x, v0.y, v0.z, v0.w},
                                   {v1.x, v1.y, v1.z, v1.w}};
#pragma unroll
        for (int mt = 0; mt < 2; mt++) {
#pragma unroll
            for (int np = 0; np < 2; np++) {
                MMA16816(acc[mt][2*np+0], ah[mt][0], ah[mt][1], ah[mt][2], ah[mt][3],
                         bh[np][0], bh[np][1]);
                MMA16816(acc[mt][2*np+1], ah[mt][0], ah[mt][1], ah[mt][2], ah[mt][3],
                         bh[np][2], bh[np][3]);
            }
        }
    }

    // ---- epilogue: 8 consecutive cols per row -> streaming STG.128 ----
    const int gid = lane >> 2, tig = lane & 3;
    const int colb = 32 * G + tig * 8;
    float bb[8];
    {
        const float4 b0v = __ldg(reinterpret_cast<const float4*>(lin_b + colb));
        const float4 b1v = __ldg(reinterpret_cast<const float4*>(lin_b + colb + 4));
        bb[0]=b0v.x; bb[1]=b0v.y; bb[2]=b0v.z; bb[3]=b0v.w;
        bb[4]=b1v.x; bb[5]=b1v.y; bb[6]=b1v.z; bb[7]=b1v.w;
    }
#pragma unroll
    for (int mt = 0; mt < 2; mt++) {
        const long row = s0 + 32 * q + mt * 16 + gid;
        float* ob = out + ((long)b * Sn + row) * Pn + colb;
        float4 r0a = make_float4(acc[mt][0][0]+bb[0], acc[mt][0][1]+bb[1],
                                 acc[mt][1][0]+bb[2], acc[mt][1][1]+bb[3]);
        float4 r0b = make_float4(acc[mt][2][0]+bb[4], acc[mt][2][1]+bb[5],
                                 acc[mt][3][0]+bb[6], acc[mt][3][1]+bb[7]);
        float4 r1a = make_float4(acc[mt][0][2]+bb[0], acc[mt][0][3]+bb[1],
                                 acc[mt][1][2]+bb[2], acc[mt][1][3]+bb[3]);
        float4 r1b = make_float4(acc[mt][2][2]+bb[4], acc[mt][2][3]+bb[5],
                                 acc[mt][3][2]+bb[6], acc[mt][3][3]+bb[7]);
        __stcs(reinterpret_cast<float4*>(ob),              r0a);
        __stcs(reinterpret_cast<float4*>(ob + 4),          r0b);
        __stcs(reinterpret_cast<float4*>(ob + 8 * Pn),     r1a);
        __stcs(reinterpret_cast<float4*>(ob + 8 * Pn + 4), r1b);
    }
}

extern "C" void kernel_launch(void* const* d_in, const int* in_sizes, int n_in,
                              void* d_out, int out_size) {
    (void)in_sizes; (void)n_in; (void)out_size;
    const float* x      = (const float*)d_in[0];
    const float* conv_w = (const float*)d_in[1];
    const float* conv_b = (const float*)d_in[2];
    const float* lin_w  = (const float*)d_in[3];
    const float* lin_b  = (const float*)d_in[4];
    float* out = (float*)d_out;

    pack_w_kernel<<<2, 256>>>(lin_w);
    pack_c_kernel<<<1, 32>>>(conv_w, conv_b);

    cudaFuncSetAttribute(encoder_kernel,
                         cudaFuncAttributeMaxDynamicSharedMemorySize, SMEM_TOTAL);
    dim3 grid((unsigned)(Sn / S_TILE), Bn);
    encoder_kernel<<<grid, THREADS, SMEM_TOTAL>>>(x, lin_b, out);
}

// round 14
// speedup vs baseline: 1.5864x; 1.5864x over previous
#include <cuda_runtime.h>
#include <cuda_fp16.h>
#include <cstdint>

namespace {
constexpr int  Bn = 8;
constexpr long Tn = 262144;
constexpr long Sn = 131072;   // output positions
constexpr int  En = 128;      // conv channels = GEMM K
constexpr int  Pn = 64;       // out features  = GEMM N
constexpr int  S_TILE = 128;  // GEMM M per CTA
constexpr int  THREADS = 256;
constexpr int  LDA = 136;     // halves/row, padded -> conflict-free ldmatrix

constexpr int SMEM_TOTAL = S_TILE * LDA * 2;   // 34816 B -> 4 CTAs/SM
}

// B fragments, lane-contiguous: [G(2)][chunk(8)][pair(2)][lane(32)] of uint4
__device__ uint4 g_bfrag[2 * 8 * 2 * 32];
// packed conv taps: [slot(3)][lane(32)] of uint4 (12 half2 per lane)
__device__ uint4 g_cpack[3 * 32];

__device__ __forceinline__ uint32_t smem_u32(const void* p) {
    return (uint32_t)__cvta_generic_to_shared(p);
}
__device__ __forceinline__ __half2 u2h(uint32_t u) {
    return *reinterpret_cast<const __half2*>(&u);
}

#define LDSM_X4(r0, r1, r2, r3, addr)                                            \
    asm volatile("ldmatrix.sync.aligned.m8n8.x4.shared.b16 {%0,%1,%2,%3}, [%4];" \
                 : "=r"(r0), "=r"(r1), "=r"(r2), "=r"(r3) : "r"(addr))

#define MMA16816(d, a0, a1, a2, a3, b0, b1)                                      \
    asm volatile("mma.sync.aligned.m16n8k16.row.col.f32.f16.f16.f32 "            \
                 "{%0,%1,%2,%3},{%4,%5,%6,%7},{%8,%9},{%0,%1,%2,%3};"            \
                 : "+f"((d)[0]), "+f"((d)[1]), "+f"((d)[2]), "+f"((d)[3])        \
                 : "r"(a0), "r"(a1), "r"(a2), "r"(a3), "r"(b0), "r"(b1))

// ---- init: blocks 0-1 pack lin_w into B fragments; block 2 packs conv taps ----
__global__ void pack_kernel(const float* __restrict__ lin_w,
                            const float* __restrict__ conv_w,
                            const float* __restrict__ conv_b) {
    if (blockIdx.x < 2) {
        const int idx = blockIdx.x * blockDim.x + threadIdx.x;   // 0..511
        const int lane  = idx & 31;
        const int chunk = (idx >> 5) & 7;
        const int G     = idx >> 8;
        uint32_t r[8];
#pragma unroll
        for (int s = 0; s < 2; s++) {
#pragma unroll
            for (int q = 0; q < 4; q++) {
                const int nt = 2 * s + (q >> 1);
                const int n  = 32 * G + (lane >> 3) * 8 + nt * 2 + ((lane >> 2) & 1);
                const int k  = 16 * chunk + ((q & 1) << 3) + ((lane & 3) << 1);
                const float2 w = *reinterpret_cast<const float2*>(lin_w + n * En + k);
                __half2 h = __halves2half2(__float2half_rn(w.x), __float2half_rn(w.y));
                r[s * 4 + q] = *reinterpret_cast<const uint32_t*>(&h);
            }
        }
        g_bfrag[((G * 8 + chunk) * 2 + 0) * 32 + lane] = make_uint4(r[0], r[1], r[2], r[3]);
        g_bfrag[((G * 8 + chunk) * 2 + 1) * 32 + lane] = make_uint4(r[4], r[5], r[6], r[7]);
    } else if (threadIdx.x < 32) {
        const int lane = threadIdx.x;
        const int c0 = 4 * lane;
        const float4* cw4 = reinterpret_cast<const float4*>(conv_w + 5 * c0);
        float4 q0 = cw4[0], q1 = cw4[1], q2 = cw4[2], q3 = cw4[3], q4 = cw4[4];
        float4 bbv = *reinterpret_cast<const float4*>(conv_b + c0);
        __half2 h[12];
        h[0]  = __floats2half2_rn(q0.x, q1.y);   // wA0
        h[1]  = __floats2half2_rn(q0.y, q1.z);   // wA1
        h[2]  = __floats2half2_rn(q0.z, q1.w);   // wA2
        h[3]  = __floats2half2_rn(q0.w, q2.x);   // wA3
        h[4]  = __floats2half2_rn(q1.x, q2.y);   // wA4
        h[5]  = __floats2half2_rn(q2.z, q3.w);   // wB0
        h[6]  = __floats2half2_rn(q2.w, q4.x);   // wB1
        h[7]  = __floats2half2_rn(q3.x, q4.y);   // wB2
        h[8]  = __floats2half2_rn(q3.y, q4.z);   // wB3
        h[9]  = __floats2half2_rn(q3.z, q4.w);   // wB4
        h[10] = __floats2half2_rn(bbv.x, bbv.y); // cbA
        h[11] = __floats2half2_rn(bbv.z, bbv.w); // cbB
        const uint32_t* u = reinterpret_cast<const uint32_t*>(h);
        g_cpack[0 * 32 + lane] = make_uint4(u[0], u[1], u[2],  u[3]);
        g_cpack[1 * 32 + lane] = make_uint4(u[4], u[5], u[6],  u[7]);
        g_cpack[2 * 32 + lane] = make_uint4(u[8], u[9], u[10], u[11]);
    }
}

__global__ void __launch_bounds__(THREADS, 4)
encoder_kernel(const float* __restrict__ x,       // [B, T]
               const float* __restrict__ lin_b,   // [64]
               float* __restrict__ out)           // [B, S, 64]
{
    extern __shared__ char smem[];
    __half* fhi = (__half*)smem;

    const int tid  = threadIdx.x;
    const int wid  = tid >> 5;
    const int lane = tid & 31;
    const int b    = blockIdx.y;
    const long s0  = (long)blockIdx.x * S_TILE;
    const int q    = wid & 3;        // pipeline pair {q, q+4}
    const int G    = wid >> 2;       // n-group

    // ---- conv taps: 3 coalesced LDG.128 of pre-packed half2 ----
    const int c0 = 4 * lane;
    const int pb = 32 * q + 16 * G;              // this warp's 16 A rows
    __half2 wA[5], wB[5], cbA, cbB;
    {
        const uint4 v0 = __ldg(g_cpack + lane);
        const uint4 v1 = __ldg(g_cpack + 32 + lane);
        const uint4 v2 = __ldg(g_cpack + 64 + lane);
        wA[0]=u2h(v0.x); wA[1]=u2h(v0.y); wA[2]=u2h(v0.z); wA[3]=u2h(v0.w);
        wA[4]=u2h(v1.x); wB[0]=u2h(v1.y); wB[1]=u2h(v1.z); wB[2]=u2h(v1.w);
        wB[3]=u2h(v2.x); wB[4]=u2h(v2.y); cbA =u2h(v2.z); cbB =u2h(v2.w);
    }

    // ---- warp-private input window in registers (35 floats across lanes) ----
    const long t0w = 2L * (s0 + pb) - 2;
    float xv0, xv1;
    {
        const float* xb = x + (long)b * Tn;
        long t = t0w + lane;
        xv0 = (t >= 0 && t < Tn) ? xb[t] : 0.f;
        t += 32;
        xv1 = (t >= 0 && t < Tn) ? xb[t] : 0.f;
    }

    // ---- conv1d + ReLU in half2 -> A rows pb..pb+15 ----
    {
        const unsigned m = 0xFFFFFFFFu;
        const __half2 hzero = __float2half2_rn(0.f);
        __half2 X0 = __float2half2_rn(__shfl_sync(m, xv0, 0));
        __half2 X1 = __float2half2_rn(__shfl_sync(m, xv0, 1));
        __half2 X2 = __float2half2_rn(__shfl_sync(m, xv0, 2));
        __half2 X3 = __float2half2_rn(__shfl_sync(m, xv0, 3));
        __half2 X4 = __float2half2_rn(__shfl_sync(m, xv0, 4));
#pragma unroll
        for (int p = 0; p < 16; p++) {
            __half2 vA = __hfma2(wA[0], X0, cbA);
            vA = __hfma2(wA[1], X1, vA);
            vA = __hfma2(wA[2], X2, vA);
            vA = __hfma2(wA[3], X3, vA);
            vA = __hfma2(wA[4], X4, vA);
            vA = __hmax2(vA, hzero);
            __half2 vB = __hfma2(wB[0], X0, cbB);
            vB = __hfma2(wB[1], X1, vB);
            vB = __hfma2(wB[2], X2, vB);
            vB = __hfma2(wB[3], X3, vB);
            vB = __hfma2(wB[4], X4, vB);
            vB = __hmax2(vB, hzero);
            uint2 vh;
            vh.x = *reinterpret_cast<const uint32_t*>(&vA);
            vh.y = *reinterpret_cast<const uint32_t*>(&vB);
            *reinterpret_cast<uint2*>(fhi + (pb + p) * LDA + c0) = vh;
            if (p < 15) {
                X0 = X2; X1 = X3; X2 = X4;
                const int i5 = 2 * p + 5, i6 = 2 * p + 6;   // compile-time consts
                float f3 = (i5 < 32) ? __shfl_sync(m, xv0, i5) : __shfl_sync(m, xv1, i5 - 32);
                float f4 = (i6 < 32) ? __shfl_sync(m, xv0, i6) : __shfl_sync(m, xv1, i6 - 32);
                X3 = __float2half2_rn(f3);
                X4 = __float2half2_rn(f4);
            }
        }
    }

    // pairwise producer/consumer barrier: warps {q, q+4} (drains STS)
    asm volatile("bar.sync %0, 64;" :: "r"(q) : "memory");

    // ---- GEMM: warp tile m32 x n32 on rows 32q..32q+31 ----
    float acc[2][4][4];
#pragma unroll
    for (int mt = 0; mt < 2; mt++)
#pragma unroll
        for (int nt = 0; nt < 4; nt++)
#pragma unroll
            for (int qq = 0; qq < 4; qq++) acc[mt][nt][qq] = 0.f;

    const int aoff0 = (32 * q + (lane & 15)) * LDA + ((lane >> 4) << 3);
    const uint32_t a_s0 = smem_u32(fhi + aoff0);
    const uint32_t a_s1 = smem_u32(fhi + aoff0 + 16 * LDA);
    const uint4* bp = g_bfrag + (G * 8) * 2 * 32 + lane;

#pragma unroll
    for (int c = 0; c < 8; c++) {
        const uint32_t kB = c * 32;
        uint32_t ah[2][4];
        LDSM_X4(ah[0][0], ah[0][1], ah[0][2], ah[0][3], a_s0 + kB);
        LDSM_X4(ah[1][0], ah[1][1], ah[1][2], ah[1][3], a_s1 + kB);
        const uint4 v0 = __ldg(bp + c * 64);
        const uint4 v1 = __ldg(bp + c * 64 + 32);
        const uint32_t bh[2][4] = {{v0.x, v0.y, v0.z, v0.w},
                                   {v1.x, v1.y, v1.z, v1.w}};
#pragma unroll
        for (int mt = 0; mt < 2; mt++) {
#pragma unroll
            for (int np = 0; np < 2; np++) {
                MMA16816(acc[mt][2*np+0], ah[mt][0], ah[mt][1], ah[mt][2], ah[mt][3],
                         bh[np][0], bh[np][1]);
                MMA16816(acc[mt][2*np+1], ah[mt][0], ah[mt][1], ah[mt][2], ah[mt][3],
                         bh[np][2], bh[np][3]);
            }
        }
    }

    // ---- epilogue: 8 consecutive cols per row -> streaming STG.128 ----
    const int gid = lane >> 2, tig = lane & 3;
    const int colb = 32 * G + tig * 8;
    float bb[8];
    {
        const float4 b0v = __ldg(reinterpret_cast<const float4*>(lin_b + colb));
        const float4 b1v = __ldg(reinterpret_cast<const float4*>(lin_b + colb + 4));
        bb[0]=b0v.x; bb[1]=b0v.y; bb[2]=b0v.z; bb[3]=b0v.w;
        bb[4]=b1v.x; bb[5]=b1v.y; bb[6]=b1v.z; bb[7]=b1v.w;
    }
#pragma unroll
    for (int mt = 0; mt < 2; mt++) {
        const long row = s0 + 32 * q + mt * 16 + gid;
        float* ob = out + ((long)b * Sn + row) * Pn + colb;
        float4 r0a = make_float4(acc[mt][0][0]+bb[0], acc[mt][0][1]+bb[1],
                                 acc[mt][1][0]+bb[2], acc[mt][1][1]+bb[3]);
        float4 r0b = make_float4(acc[mt][2][0]+bb[4], acc[mt][2][1]+bb[5],
                                 acc[mt][3][0]+bb[6], acc[mt][3][1]+bb[7]);
        float4 r1a = make_float4(acc[mt][0][2]+bb[0], acc[mt][0][3]+bb[1],
                                 acc[mt][1][2]+bb[2], acc[mt][1][3]+bb[3]);
        float4 r1b = make_float4(acc[mt][2][2]+bb[4], acc[mt][2][3]+bb[5],
                                 acc[mt][3][2]+bb[6], acc[mt][3][3]+bb[7]);
        __stcs(reinterpret_cast<float4*>(ob),              r0a);
        __stcs(reinterpret_cast<float4*>(ob + 4),          r0b);
        __stcs(reinterpret_cast<float4*>(ob + 8 * Pn),     r1a);
        __stcs(reinterpret_cast<float4*>(ob + 8 * Pn + 4), r1b);
    }
}

extern "C" void kernel_launch(void* const* d_in, const int* in_sizes, int n_in,
                              void* d_out, int out_size) {
    (void)in_sizes; (void)n_in; (void)out_size;
    const float* x      = (const float*)d_in[0];
    const float* conv_w = (const float*)d_in[1];
    const float* conv_b = (const float*)d_in[2];
    const float* lin_w  = (const float*)d_in[3];
    const float* lin_b  = (const float*)d_in[4];
    float* out = (float*)d_out;

    pack_kernel<<<3, 256>>>(lin_w, conv_w, conv_b);

    cudaFuncSetAttribute(encoder_kernel,
                         cudaFuncAttributeMaxDynamicSharedMemorySize, SMEM_TOTAL);
    dim3 grid((unsigned)(Sn / S_TILE), Bn);
    encoder_kernel<<<grid, THREADS, SMEM_TOTAL>>>(x, lin_b, out);
}

// round 15
// speedup vs baseline: 1.8088x; 1.1402x over previous
#include <cuda_runtime.h>
#include <cuda_fp16.h>
#include <cstdint>

namespace {
constexpr int  Bn = 8;
constexpr long Tn = 262144;
constexpr long Sn = 131072;   // output positions
constexpr int  En = 128;      // conv channels = GEMM K
constexpr int  Pn = 64;       // out features  = GEMM N
constexpr int  S_TILE = 128;  // GEMM M per CTA
constexpr int  THREADS = 256;
constexpr int  LDA = 136;     // halves/row, padded -> conflict-free ldmatrix

constexpr int SMEM_TOTAL = S_TILE * LDA * 2;   // 34816 B -> 4 CTAs/SM
}

// B fragments, lane-contiguous: [G(2)][chunk(8)][pair(2)][lane(32)] of uint4
__device__ uint4 g_bfrag[2 * 8 * 2 * 32];

__device__ __forceinline__ uint32_t smem_u32(const void* p) {
    return (uint32_t)__cvta_generic_to_shared(p);
}

#define LDSM_X4(r0, r1, r2, r3, addr)                                            \
    asm volatile("ldmatrix.sync.aligned.m8n8.x4.shared.b16 {%0,%1,%2,%3}, [%4];" \
                 : "=r"(r0), "=r"(r1), "=r"(r2), "=r"(r3) : "r"(addr))

#define MMA16816(d, a0, a1, a2, a3, b0, b1)                                      \
    asm volatile("mma.sync.aligned.m16n8k16.row.col.f32.f16.f16.f32 "            \
                 "{%0,%1,%2,%3},{%4,%5,%6,%7},{%8,%9},{%0,%1,%2,%3};"            \
                 : "+f"((d)[0]), "+f"((d)[1]), "+f"((d)[2]), "+f"((d)[3])        \
                 : "r"(a0), "r"(a1), "r"(a2), "r"(a3), "r"(b0), "r"(b1))

// ---- init: pack lin_w (fp32 [64,128]) into fp16 B fragments ----
// N-permutation: logical col = 32*G + (vn>>1)*8 + nt*2 + (vn&1) so each
// D-fragment thread owns 8 consecutive output columns per row.
__global__ void pack_w_kernel(const float* __restrict__ lin_w) {
    const int idx = blockIdx.x * blockDim.x + threadIdx.x;   // 512 threads
    if (idx >= 2 * 8 * 32) return;
    const int lane  = idx & 31;
    const int chunk = (idx >> 5) & 7;
    const int G     = idx >> 8;

    uint32_t r[8];
#pragma unroll
    for (int s = 0; s < 2; s++) {
#pragma unroll
        for (int q = 0; q < 4; q++) {
            const int nt = 2 * s + (q >> 1);
            const int n  = 32 * G + (lane >> 3) * 8 + nt * 2 + ((lane >> 2) & 1);
            const int k  = 16 * chunk + ((q & 1) << 3) + ((lane & 3) << 1);
            const float2 w = *reinterpret_cast<const float2*>(lin_w + n * En + k);
            __half2 h = __halves2half2(__float2half_rn(w.x), __float2half_rn(w.y));
            r[s * 4 + q] = *reinterpret_cast<const uint32_t*>(&h);
        }
    }
    g_bfrag[((G * 8 + chunk) * 2 + 0) * 32 + lane] = make_uint4(r[0], r[1], r[2], r[3]);
    g_bfrag[((G * 8 + chunk) * 2 + 1) * 32 + lane] = make_uint4(r[4], r[5], r[6], r[7]);
}

__global__ void __launch_bounds__(THREADS, 4)
encoder_kernel(const float* __restrict__ x,       // [B, T]
               const float* __restrict__ conv_w,  // [128, 1, 5]
               const float* __restrict__ conv_b,  // [128]
               const float* __restrict__ lin_b,   // [64]
               float* __restrict__ out)           // [B, S, 64]
{
    extern __shared__ char smem[];
    __half* fhi = (__half*)smem;

    const int tid  = threadIdx.x;
    const int wid  = tid >> 5;
    const int lane = tid & 31;
    const int b    = blockIdx.y;
    const long s0  = (long)blockIdx.x * S_TILE;
    const int q    = wid & 3;        // pipeline pair {q, q+4}
    const int G    = wid >> 2;       // n-group

    // ---- conv taps as half2 (channels c0,c0+1 | c0+2,c0+3) ----
    const int c0 = 4 * lane;
    const int pb = 32 * q + 16 * G;              // this warp's 16 A rows
    __half2 wA[5], wB[5], cbA, cbB;
    {
        const float4* cw4 = reinterpret_cast<const float4*>(conv_w + 5 * c0);
        float4 q0 = cw4[0], q1 = cw4[1], q2 = cw4[2], q3 = cw4[3], q4 = cw4[4];
        // ch0 taps: q0.x..q1.x ; ch1: q1.y..q2.y ; ch2: q2.z..q3.z ; ch3: q3.w..q4.w
        wA[0] = __floats2half2_rn(q0.x, q1.y);
        wA[1] = __floats2half2_rn(q0.y, q1.z);
        wA[2] = __floats2half2_rn(q0.z, q1.w);
        wA[3] = __floats2half2_rn(q0.w, q2.x);
        wA[4] = __floats2half2_rn(q1.x, q2.y);
        wB[0] = __floats2half2_rn(q2.z, q3.w);
        wB[1] = __floats2half2_rn(q2.w, q4.x);
        wB[2] = __floats2half2_rn(q3.x, q4.y);
        wB[3] = __floats2half2_rn(q3.y, q4.z);
        wB[4] = __floats2half2_rn(q3.z, q4.w);
        float4 bbv = *reinterpret_cast<const float4*>(conv_b + c0);
        cbA = __floats2half2_rn(bbv.x, bbv.y);
        cbB = __floats2half2_rn(bbv.z, bbv.w);
    }

    // ---- warp-private input window in registers (35 floats across lanes) ----
    const long t0w = 2L * (s0 + pb) - 2;
    float xv0, xv1;
    {
        const float* xb = x + (long)b * Tn;
        long t = t0w + lane;
        xv0 = (t >= 0 && t < Tn) ? xb[t] : 0.f;
        t += 32;
        xv1 = (t >= 0 && t < Tn) ? xb[t] : 0.f;
    }

    // ---- conv1d + ReLU in half2 -> A rows pb..pb+15 ----
    {
        const unsigned m = 0xFFFFFFFFu;
        const __half2 hzero = __float2half2_rn(0.f);
        __half2 X0 = __float2half2_rn(__shfl_sync(m, xv0, 0));
        __half2 X1 = __float2half2_rn(__shfl_sync(m, xv0, 1));
        __half2 X2 = __float2half2_rn(__shfl_sync(m, xv0, 2));
        __half2 X3 = __float2half2_rn(__shfl_sync(m, xv0, 3));
        __half2 X4 = __float2half2_rn(__shfl_sync(m, xv0, 4));
#pragma unroll
        for (int p = 0; p < 16; p++) {
            __half2 vA = __hfma2(wA[0], X0, cbA);
            vA = __hfma2(wA[1], X1, vA);
            vA = __hfma2(wA[2], X2, vA);
            vA = __hfma2(wA[3], X3, vA);
            vA = __hfma2(wA[4], X4, vA);
            vA = __hmax2(vA, hzero);
            __half2 vB = __hfma2(wB[0], X0, cbB);
            vB = __hfma2(wB[1], X1, vB);
            vB = __hfma2(wB[2], X2, vB);
            vB = __hfma2(wB[3], X3, vB);
            vB = __hfma2(wB[4], X4, vB);
            vB = __hmax2(vB, hzero);
            uint2 vh;
            vh.x = *reinterpret_cast<const uint32_t*>(&vA);
            vh.y = *reinterpret_cast<const uint32_t*>(&vB);
            *reinterpret_cast<uint2*>(fhi + (pb + p) * LDA + c0) = vh;
            if (p < 15) {
                X0 = X2; X1 = X3; X2 = X4;
                const int i5 = 2 * p + 5, i6 = 2 * p + 6;   // compile-time consts
                float f3 = (i5 < 32) ? __shfl_sync(m, xv0, i5) : __shfl_sync(m, xv1, i5 - 32);
                float f4 = (i6 < 32) ? __shfl_sync(m, xv0, i6) : __shfl_sync(m, xv1, i6 - 32);
                X3 = __float2half2_rn(f3);
                X4 = __float2half2_rn(f4);
            }
        }
    }

    // pairwise producer/consumer barrier: warps {q, q+4} (drains STS)
    asm volatile("bar.sync %0, 64;" :: "r"(q) : "memory");

    // ---- GEMM: warp tile m32 x n32 on rows 32q..32q+31 ----
    float acc[2][4][4];
#pragma unroll
    for (int mt = 0; mt < 2; mt++)
#pragma unroll
        for (int nt = 0; nt < 4; nt++)
#pragma unroll
            for (int qq = 0; qq < 4; qq++) acc[mt][nt][qq] = 0.f;

    const int aoff0 = (32 * q + (lane & 15)) * LDA + ((lane >> 4) << 3);
    const uint32_t a_s0 = smem_u32(fhi + aoff0);
    const uint32_t a_s1 = smem_u32(fhi + aoff0 + 16 * LDA);
    const uint4* bp = g_bfrag + (G * 8) * 2 * 32 + lane;

#pragma unroll
    for (int c = 0; c < 8; c++) {
        const uint32_t kB = c * 32;
        uint32_t ah[2][4];
        LDSM_X4(ah[0][0], ah[0][1], ah[0][2], ah[0][3], a_s0 + kB);
        LDSM_X4(ah[1][0], ah[1][1], ah[1][2], ah[1][3], a_s1 + kB);
        const uint4 v0 = __ldg(bp + c * 64);
        const uint4 v1 = __ldg(bp + c * 64 + 32);
        const uint32_t bh[2][4] = {{v0.x, v0.y, v0.z, v0.w},
                                   {v1.x, v1.y, v1.z, v1.w}};
#pragma unroll
        for (int mt = 0; mt < 2; mt++) {
#pragma unroll
            for (int np = 0; np < 2; np++) {
                MMA16816(acc[mt][2*np+0], ah[mt][0], ah[mt][1], ah[mt][2], ah[mt][3],
                         bh[np][0], bh[np][1]);
                MMA16816(acc[mt][2*np+1], ah[mt][0], ah[mt][1], ah[mt][2], ah[mt][3],
                         bh[np][2], bh[np][3]);
            }
        }
    }

    // ---- epilogue: 8 consecutive cols per row -> streaming STG.128 ----
    const int gid = lane >> 2, tig = lane & 3;
    const int colb = 32 * G + tig * 8;
    float bb[8];
    {
        const float4 b0v = __ldg(reinterpret_cast<const float4*>(lin_b + colb));
        const float4 b1v = __ldg(reinterpret_cast<const float4*>(lin_b + colb + 4));
        bb[0]=b0v.x; bb[1]=b0v.y; bb[2]=b0v.z; bb[3]=b0v.w;
        bb[4]=b1v.x; bb[5]=b1v.y; bb[6]=b1v.z; bb[7]=b1v.w;
    }
#pragma unroll
    for (int mt = 0; mt < 2; mt++) {
        const long row = s0 + 32 * q + mt * 16 + gid;
        float* ob = out + ((long)b * Sn + row) * Pn + colb;
        float4 r0a = make_float4(acc[mt][0][0]+bb[0], acc[mt][0][1]+bb[1],
                                 acc[mt][1][0]+bb[2], acc[mt][1][1]+bb[3]);
        float4 r0b = make_float4(acc[mt][2][0]+bb[4], acc[mt][2][1]+bb[5],
                                 acc[mt][3][0]+bb[6], acc[mt][3][1]+bb[7]);
        float4 r1a = make_float4(acc[mt][0][2]+bb[0], acc[mt][0][3]+bb[1],
                                 acc[mt][1][2]+bb[2], acc[mt][1][3]+bb[3]);
        float4 r1b = make_float4(acc[mt][2][2]+bb[4], acc[mt][2][3]+bb[5],
                                 acc[mt][3][2]+bb[6], acc[mt][3][3]+bb[7]);
        __stcs(reinterpret_cast<float4*>(ob),              r0a);
        __stcs(reinterpret_cast<float4*>(ob + 4),          r0b);
        __stcs(reinterpret_cast<float4*>(ob + 8 * Pn),     r1a);
        __stcs(reinterpret_cast<float4*>(ob + 8 * Pn + 4), r1b);
    }
}

extern "C" void kernel_launch(void* const* d_in, const int* in_sizes, int n_in,
                              void* d_out, int out_size) {
    (void)in_sizes; (void)n_in; (void)out_size;
    const float* x      = (const float*)d_in[0];
    const float* conv_w = (const float*)d_in[1];
    const float* conv_b = (const float*)d_in[2];
    const float* lin_w  = (const float*)d_in[3];
    const float* lin_b  = (const float*)d_in[4];
    float* out = (float*)d_out;

    pack_w_kernel<<<2, 256>>>(lin_w);

    cudaFuncSetAttribute(encoder_kernel,
                         cudaFuncAttributeMaxDynamicSharedMemorySize, SMEM_TOTAL);
    dim3 grid((unsigned)(Sn / S_TILE), Bn);
    encoder_kernel<<<grid, THREADS, SMEM_TOTAL>>>(x, conv_w, conv_b, lin_b, out);
}

// round 16
// speedup vs baseline: 1.8094x; 1.0003x over previous
#include <cuda_runtime.h>
#include <cuda_fp16.h>
#include <cstdint>

namespace {
constexpr int  Bn = 8;
constexpr long Tn = 262144;
constexpr long Sn = 131072;   // output positions
constexpr int  En = 128;      // conv channels = GEMM K
constexpr int  Pn = 64;       // out features  = GEMM N
constexpr int  S_TILE = 128;  // GEMM M per CTA
constexpr int  THREADS = 256;
constexpr int  LDA = 136;     // halves/row, padded -> conflict-free ldmatrix

constexpr int SMEM_TOTAL = S_TILE * LDA * 2;   // 34816 B -> 4 CTAs/SM
}

// B fragments, lane-contiguous: [G(2)][chunk(8)][pair(2)][lane(32)] of uint4
__device__ uint4 g_bfrag[2 * 8 * 2 * 32];

__device__ __forceinline__ uint32_t smem_u32(const void* p) {
    return (uint32_t)__cvta_generic_to_shared(p);
}

#define LDSM_X4(r0, r1, r2, r3, addr)                                            \
    asm volatile("ldmatrix.sync.aligned.m8n8.x4.shared.b16 {%0,%1,%2,%3}, [%4];" \
                 : "=r"(r0), "=r"(r1), "=r"(r2), "=r"(r3) : "r"(addr))

#define MMA16816(d, a0, a1, a2, a3, b0, b1)                                      \
    asm volatile("mma.sync.aligned.m16n8k16.row.col.f32.f16.f16.f32 "            \
                 "{%0,%1,%2,%3},{%4,%5,%6,%7},{%8,%9},{%0,%1,%2,%3};"            \
                 : "+f"((d)[0]), "+f"((d)[1]), "+f"((d)[2]), "+f"((d)[3])        \
                 : "r"(a0), "r"(a1), "r"(a2), "r"(a3), "r"(b0), "r"(b1))

// ---- init: pack lin_w (fp32 [64,128]) into fp16 B fragments ----
// N-permutation: logical col = 32*G + (vn>>1)*8 + nt*2 + (vn&1) so each
// D-fragment thread owns 8 consecutive output columns per row.
__global__ void pack_w_kernel(const float* __restrict__ lin_w) {
    const int idx = blockIdx.x * blockDim.x + threadIdx.x;   // 512 threads
    if (idx >= 2 * 8 * 32) return;
    const int lane  = idx & 31;
    const int chunk = (idx >> 5) & 7;
    const int G     = idx >> 8;

    uint32_t r[8];
#pragma unroll
    for (int s = 0; s < 2; s++) {
#pragma unroll
        for (int q = 0; q < 4; q++) {
            const int nt = 2 * s + (q >> 1);
            const int n  = 32 * G + (lane >> 3) * 8 + nt * 2 + ((lane >> 2) & 1);
            const int k  = 16 * chunk + ((q & 1) << 3) + ((lane & 3) << 1);
            const float2 w = *reinterpret_cast<const float2*>(lin_w + n * En + k);
            __half2 h = __halves2half2(__float2half_rn(w.x), __float2half_rn(w.y));
            r[s * 4 + q] = *reinterpret_cast<const uint32_t*>(&h);
        }
    }
    g_bfrag[((G * 8 + chunk) * 2 + 0) * 32 + lane] = make_uint4(r[0], r[1], r[2], r[3]);
    g_bfrag[((G * 8 + chunk) * 2 + 1) * 32 + lane] = make_uint4(r[4], r[5], r[6], r[7]);
}

__global__ void __launch_bounds__(THREADS, 4)
encoder_kernel(const float* __restrict__ x,       // [B, T]
               const float* __restrict__ conv_w,  // [128, 1, 5]
               const float* __restrict__ conv_b,  // [128]
               const float* __restrict__ lin_b,   // [64]
               float* __restrict__ out)           // [B, S, 64]
{
    extern __shared__ char smem[];
    __half* fhi = (__half*)smem;

    const int tid  = threadIdx.x;
    const int wid  = tid >> 5;
    const int lane = tid & 31;
    const int b    = blockIdx.y;
    const long s0  = (long)blockIdx.x * S_TILE;
    const int q    = wid & 3;        // pipeline pair {q, q+4}
    const int G    = wid >> 2;       // n-group

    // ---- conv taps as half2 (channels c0,c0+1 | c0+2,c0+3) ----
    const int c0 = 4 * lane;
    const int pb = 32 * q + 16 * G;              // this warp's 16 A rows
    __half2 wA[5], wB[5], cbA, cbB;
    {
        const float4* cw4 = reinterpret_cast<const float4*>(conv_w + 5 * c0);
        float4 q0 = cw4[0], q1 = cw4[1], q2 = cw4[2], q3 = cw4[3], q4 = cw4[4];
        wA[0] = __floats2half2_rn(q0.x, q1.y);
        wA[1] = __floats2half2_rn(q0.y, q1.z);
        wA[2] = __floats2half2_rn(q0.z, q1.w);
        wA[3] = __floats2half2_rn(q0.w, q2.x);
        wA[4] = __floats2half2_rn(q1.x, q2.y);
        wB[0] = __floats2half2_rn(q2.z, q3.w);
        wB[1] = __floats2half2_rn(q2.w, q4.x);
        wB[2] = __floats2half2_rn(q3.x, q4.y);
        wB[3] = __floats2half2_rn(q3.y, q4.z);
        wB[4] = __floats2half2_rn(q3.z, q4.w);
        float4 bbv = *reinterpret_cast<const float4*>(conv_b + c0);
        cbA = __floats2half2_rn(bbv.x, bbv.y);
        cbB = __floats2half2_rn(bbv.z, bbv.w);
    }

    // ---- warp-private input window in registers (35 floats across lanes) ----
    const long t0w = 2L * (s0 + pb) - 2;
    float xv0, xv1;
    {
        const float* xb = x + (long)b * Tn;
        long t = t0w + lane;
        xv0 = (t >= 0 && t < Tn) ? xb[t] : 0.f;
        t += 32;
        xv1 = (t >= 0 && t < Tn) ? xb[t] : 0.f;
    }

    // ---- conv1d + ReLU in half2 -> A rows pb..pb+15 ----
    {
        const unsigned m = 0xFFFFFFFFu;
        const __half2 hzero = __float2half2_rn(0.f);
        __half2 X0 = __float2half2_rn(__shfl_sync(m, xv0, 0));
        __half2 X1 = __float2half2_rn(__shfl_sync(m, xv0, 1));
        __half2 X2 = __float2half2_rn(__shfl_sync(m, xv0, 2));
        __half2 X3 = __float2half2_rn(__shfl_sync(m, xv0, 3));
        __half2 X4 = __float2half2_rn(__shfl_sync(m, xv0, 4));
#pragma unroll
        for (int p = 0; p < 16; p++) {
            __half2 vA = __hfma2(wA[0], X0, cbA);
            vA = __hfma2(wA[1], X1, vA);
            vA = __hfma2(wA[2], X2, vA);
            vA = __hfma2(wA[3], X3, vA);
            vA = __hfma2(wA[4], X4, vA);
            vA = __hmax2(vA, hzero);
            __half2 vB = __hfma2(wB[0], X0, cbB);
            vB = __hfma2(wB[1], X1, vB);
            vB = __hfma2(wB[2], X2, vB);
            vB = __hfma2(wB[3], X3, vB);
            vB = __hfma2(wB[4], X4, vB);
            vB = __hmax2(vB, hzero);
            uint2 vh;
            vh.x = *reinterpret_cast<const uint32_t*>(&vA);
            vh.y = *reinterpret_cast<const uint32_t*>(&vB);
            *reinterpret_cast<uint2*>(fhi + (pb + p) * LDA + c0) = vh;
            if (p < 15) {
                X0 = X2; X1 = X3; X2 = X4;
                const int i5 = 2 * p + 5, i6 = 2 * p + 6;   // compile-time consts
                float f3 = (i5 < 32) ? __shfl_sync(m, xv0, i5) : __shfl_sync(m, xv1, i5 - 32);
                float f4 = (i6 < 32) ? __shfl_sync(m, xv0, i6) : __shfl_sync(m, xv1, i6 - 32);
                X3 = __float2half2_rn(f3);
                X4 = __float2half2_rn(f4);
            }
        }
    }

    // pairwise producer/consumer barrier: warps {q, q+4} (drains STS)
    asm volatile("bar.sync %0, 64;" :: "r"(q) : "memory");

    // ---- GEMM: warp tile m32 x n32; acc initialized with bias ----
    const int gid = lane >> 2, tig = lane & 3;
    const int colb = 32 * G + tig * 8;

    float acc[2][4][4];
    {
        // bias regs die at acc-init: no extra live state through the MMA loop
        const float4 b0v = __ldg(reinterpret_cast<const float4*>(lin_b + colb));
        const float4 b1v = __ldg(reinterpret_cast<const float4*>(lin_b + colb + 4));
        const float bb[8] = {b0v.x, b0v.y, b0v.z, b0v.w, b1v.x, b1v.y, b1v.z, b1v.w};
#pragma unroll
        for (int mt = 0; mt < 2; mt++)
#pragma unroll
            for (int nt = 0; nt < 4; nt++) {
                acc[mt][nt][0] = bb[((nt & 2) << 1) + (nt & 1) * 2 + 0 + ((nt & 2) ? 2 : 0)];
                acc[mt][nt][1] = acc[mt][nt][0];   // placeholder, fixed below
            }
        // explicit mapping: acc[mt][nt][{0,1}] -> cols (nt<2 ? nt*2 : 4+(nt-2)*2) ...
        // use direct assignment to avoid index gymnastics:
#pragma unroll
        for (int mt = 0; mt < 2; mt++) {
            acc[mt][0][0] = bb[0]; acc[mt][0][1] = bb[1];
            acc[mt][1][0] = bb[2]; acc[mt][1][1] = bb[3];
            acc[mt][2][0] = bb[4]; acc[mt][2][1] = bb[5];
            acc[mt][3][0] = bb[6]; acc[mt][3][1] = bb[7];
            acc[mt][0][2] = bb[0]; acc[mt][0][3] = bb[1];
            acc[mt][1][2] = bb[2]; acc[mt][1][3] = bb[3];
            acc[mt][2][2] = bb[4]; acc[mt][2][3] = bb[5];
            acc[mt][3][2] = bb[6]; acc[mt][3][3] = bb[7];
        }
    }

    const int aoff0 = (32 * q + (lane & 15)) * LDA + ((lane >> 4) << 3);
    const uint32_t a_s0 = smem_u32(fhi + aoff0);
    const uint32_t a_s1 = smem_u32(fhi + aoff0 + 16 * LDA);
    const uint4* bp = g_bfrag + (G * 8) * 2 * 32 + lane;

#pragma unroll
    for (int c = 0; c < 8; c++) {
        const uint32_t kB = c * 32;
        uint32_t ah[2][4];
        LDSM_X4(ah[0][0], ah[0][1], ah[0][2], ah[0][3], a_s0 + kB);
        LDSM_X4(ah[1][0], ah[1][1], ah[1][2], ah[1][3], a_s1 + kB);
        const uint4 v0 = __ldg(bp + c * 64);
        const uint4 v1 = __ldg(bp + c * 64 + 32);
        const uint32_t bh[2][4] = {{v0.x, v0.y, v0.z, v0.w},
                                   {v1.x, v1.y, v1.z, v1.w}};
#pragma unroll
        for (int mt = 0; mt < 2; mt++) {
#pragma unroll
            for (int np = 0; np < 2; np++) {
                MMA16816(acc[mt][2*np+0], ah[mt][0], ah[mt][1], ah[mt][2], ah[mt][3],
                         bh[np][0], bh[np][1]);
                MMA16816(acc[mt][2*np+1], ah[mt][0], ah[mt][1], ah[mt][2], ah[mt][3],
                         bh[np][2], bh[np][3]);
            }
        }
    }

    // ---- epilogue: pure pack + streaming STG.128 (bias already in acc) ----
#pragma unroll
    for (int mt = 0; mt < 2; mt++) {
        const long row = s0 + 32 * q + mt * 16 + gid;
        float* ob = out + ((long)b * Sn + row) * Pn + colb;
        float4 r0a = make_float4(acc[mt][0][0], acc[mt][0][1],
                                 acc[mt][1][0], acc[mt][1][1]);
        float4 r0b = make_float4(acc[mt][2][0], acc[mt][2][1],
                                 acc[mt][3][0], acc[mt][3][1]);
        float4 r1a = make_float4(acc[mt][0][2], acc[mt][0][3],
                                 acc[mt][1][2], acc[mt][1][3]);
        float4 r1b = make_float4(acc[mt][2][2], acc[mt][2][3],
                                 acc[mt][3][2], acc[mt][3][3]);
        __stcs(reinterpret_cast<float4*>(ob),              r0a);
        __stcs(reinterpret_cast<float4*>(ob + 4),          r0b);
        __stcs(reinterpret_cast<float4*>(ob + 8 * Pn),     r1a);
        __stcs(reinterpret_cast<float4*>(ob + 8 * Pn + 4), r1b);
    }
}

extern "C" void kernel_launch(void* const* d_in, const int* in_sizes, int n_in,
                              void* d_out, int out_size) {
    (void)in_sizes; (void)n_in; (void)out_size;
    const float* x      = (const float*)d_in[0];
    const float* conv_w = (const float*)d_in[1];
    const float* conv_b = (const float*)d_in[2];
    const float* lin_w  = (const float*)d_in[3];
    const float* lin_b  = (const float*)d_in[4];
    float* out = (float*)d_out;

    pack_w_kernel<<<2, 256>>>(lin_w);

    cudaFuncSetAttribute(encoder_kernel,
                         cudaFuncAttributeMaxDynamicSharedMemorySize, SMEM_TOTAL);
    dim3 grid((unsigned)(Sn / S_TILE), Bn);
    encoder_kernel<<<grid, THREADS, SMEM_TOTAL>>>(x, conv_w, conv_b, lin_b, out);
}

// round 17
// speedup vs baseline: 1.8435x; 1.0188x over previous
#include <cuda_runtime.h>
#include <cuda_fp16.h>
#include <cstdint>

namespace {
constexpr int  Bn = 8;
constexpr long Tn = 262144;
constexpr long Sn = 131072;   // output positions
constexpr int  En = 128;      // conv channels = GEMM K
constexpr int  Pn = 64;       // out features  = GEMM N
constexpr int  S_TILE = 64;   // GEMM M per CTA (2 m-tiles x 32)
constexpr int  THREADS = 128; // 4 warps: 2 m-tiles x 2 n-groups
constexpr int  LDA = 136;     // halves/row, padded -> conflict-free ldmatrix

constexpr int SMEM_TOTAL = S_TILE * LDA * 2;   // 17408 B -> 8 CTAs/SM
}

// B fragments, lane-contiguous: [G(2)][chunk(8)][pair(2)][lane(32)] of uint4
__device__ uint4 g_bfrag[2 * 8 * 2 * 32];

__device__ __forceinline__ uint32_t smem_u32(const void* p) {
    return (uint32_t)__cvta_generic_to_shared(p);
}

#define LDSM_X4(r0, r1, r2, r3, addr)                                            \
    asm volatile("ldmatrix.sync.aligned.m8n8.x4.shared.b16 {%0,%1,%2,%3}, [%4];" \
                 : "=r"(r0), "=r"(r1), "=r"(r2), "=r"(r3) : "r"(addr))

#define MMA16816(d, a0, a1, a2, a3, b0, b1)                                      \
    asm volatile("mma.sync.aligned.m16n8k16.row.col.f32.f16.f16.f32 "            \
                 "{%0,%1,%2,%3},{%4,%5,%6,%7},{%8,%9},{%0,%1,%2,%3};"            \
                 : "+f"((d)[0]), "+f"((d)[1]), "+f"((d)[2]), "+f"((d)[3])        \
                 : "r"(a0), "r"(a1), "r"(a2), "r"(a3), "r"(b0), "r"(b1))

// ---- init: pack lin_w (fp32 [64,128]) into fp16 B fragments ----
// N-permutation: logical col = 32*G + (vn>>1)*8 + nt*2 + (vn&1) so each
// D-fragment thread owns 8 consecutive output columns per row.
__global__ void pack_w_kernel(const float* __restrict__ lin_w) {
    const int idx = blockIdx.x * blockDim.x + threadIdx.x;   // 512 threads
    if (idx >= 2 * 8 * 32) return;
    const int lane  = idx & 31;
    const int chunk = (idx >> 5) & 7;
    const int G     = idx >> 8;

    uint32_t r[8];
#pragma unroll
    for (int s = 0; s < 2; s++) {
#pragma unroll
        for (int q = 0; q < 4; q++) {
            const int nt = 2 * s + (q >> 1);
            const int n  = 32 * G + (lane >> 3) * 8 + nt * 2 + ((lane >> 2) & 1);
            const int k  = 16 * chunk + ((q & 1) << 3) + ((lane & 3) << 1);
            const float2 w = *reinterpret_cast<const float2*>(lin_w + n * En + k);
            __half2 h = __halves2half2(__float2half_rn(w.x), __float2half_rn(w.y));
            r[s * 4 + q] = *reinterpret_cast<const uint32_t*>(&h);
        }
    }
    g_bfrag[((G * 8 + chunk) * 2 + 0) * 32 + lane] = make_uint4(r[0], r[1], r[2], r[3]);
    g_bfrag[((G * 8 + chunk) * 2 + 1) * 32 + lane] = make_uint4(r[4], r[5], r[6], r[7]);
}

__global__ void __launch_bounds__(THREADS, 8)
encoder_kernel(const float* __restrict__ x,       // [B, T]
               const float* __restrict__ conv_w,  // [128, 1, 5]
               const float* __restrict__ conv_b,  // [128]
               const float* __restrict__ lin_b,   // [64]
               float* __restrict__ out)           // [B, S, 64]
{
    extern __shared__ char smem[];
    __half* fhi = (__half*)smem;

    const int tid  = threadIdx.x;
    const int wid  = tid >> 5;
    const int lane = tid & 31;
    const int b    = blockIdx.y;
    const long s0  = (long)blockIdx.x * S_TILE;
    const int q    = wid & 1;        // m-tile / pipeline pair {q, q+2}
    const int G    = wid >> 1;       // n-group

    // ---- conv taps as half2 (channels c0,c0+1 | c0+2,c0+3) ----
    const int c0 = 4 * lane;
    const int pb = 32 * q + 16 * G;              // this warp's 16 A rows
    __half2 wA[5], wB[5], cbA, cbB;
    {
        const float4* cw4 = reinterpret_cast<const float4*>(conv_w + 5 * c0);
        float4 q0 = cw4[0], q1 = cw4[1], q2 = cw4[2], q3 = cw4[3], q4 = cw4[4];
        wA[0] = __floats2half2_rn(q0.x, q1.y);
        wA[1] = __floats2half2_rn(q0.y, q1.z);
        wA[2] = __floats2half2_rn(q0.z, q1.w);
        wA[3] = __floats2half2_rn(q0.w, q2.x);
        wA[4] = __floats2half2_rn(q1.x, q2.y);
        wB[0] = __floats2half2_rn(q2.z, q3.w);
        wB[1] = __floats2half2_rn(q2.w, q4.x);
        wB[2] = __floats2half2_rn(q3.x, q4.y);
        wB[3] = __floats2half2_rn(q3.y, q4.z);
        wB[4] = __floats2half2_rn(q3.z, q4.w);
        float4 bbv = *reinterpret_cast<const float4*>(conv_b + c0);
        cbA = __floats2half2_rn(bbv.x, bbv.y);
        cbB = __floats2half2_rn(bbv.z, bbv.w);
    }

    // ---- warp-private input window in registers (35 floats across lanes) ----
    const long t0w = 2L * (s0 + pb) - 2;
    float xv0, xv1;
    {
        const float* xb = x + (long)b * Tn;
        long t = t0w + lane;
        xv0 = (t >= 0 && t < Tn) ? xb[t] : 0.f;
        t += 32;
        xv1 = (t >= 0 && t < Tn) ? xb[t] : 0.f;
    }

    // ---- conv1d + ReLU in half2 -> A rows pb..pb+15 ----
    {
        const unsigned m = 0xFFFFFFFFu;
        const __half2 hzero = __float2half2_rn(0.f);
        __half2 X0 = __float2half2_rn(__shfl_sync(m, xv0, 0));
        __half2 X1 = __float2half2_rn(__shfl_sync(m, xv0, 1));
        __half2 X2 = __float2half2_rn(__shfl_sync(m, xv0, 2));
        __half2 X3 = __float2half2_rn(__shfl_sync(m, xv0, 3));
        __half2 X4 = __float2half2_rn(__shfl_sync(m, xv0, 4));
#pragma unroll
        for (int p = 0; p < 16; p++) {
            __half2 vA = __hfma2(wA[0], X0, cbA);
            vA = __hfma2(wA[1], X1, vA);
            vA = __hfma2(wA[2], X2, vA);
            vA = __hfma2(wA[3], X3, vA);
            vA = __hfma2(wA[4], X4, vA);
            vA = __hmax2(vA, hzero);
            __half2 vB = __hfma2(wB[0], X0, cbB);
            vB = __hfma2(wB[1], X1, vB);
            vB = __hfma2(wB[2], X2, vB);
            vB = __hfma2(wB[3], X3, vB);
            vB = __hfma2(wB[4], X4, vB);
            vB = __hmax2(vB, hzero);
            uint2 vh;
            vh.x = *reinterpret_cast<const uint32_t*>(&vA);
            vh.y = *reinterpret_cast<const uint32_t*>(&vB);
            *reinterpret_cast<uint2*>(fhi + (pb + p) * LDA + c0) = vh;
            if (p < 15) {
                X0 = X2; X1 = X3; X2 = X4;
                const int i5 = 2 * p + 5, i6 = 2 * p + 6;   // compile-time consts
                float f3 = (i5 < 32) ? __shfl_sync(m, xv0, i5) : __shfl_sync(m, xv1, i5 - 32);
                float f4 = (i6 < 32) ? __shfl_sync(m, xv0, i6) : __shfl_sync(m, xv1, i6 - 32);
                X3 = __float2half2_rn(f3);
                X4 = __float2half2_rn(f4);
            }
        }
    }

    // pairwise producer/consumer barrier: warps {q, q+2} (drains STS)
    asm volatile("bar.sync %0, 64;" :: "r"(q) : "memory");

    // ---- GEMM: warp tile m32 x n32; acc initialized with bias ----
    const int gid = lane >> 2, tig = lane & 3;
    const int colb = 32 * G + tig * 8;

    float acc[2][4][4];
    {
        const float4 b0v = __ldg(reinterpret_cast<const float4*>(lin_b + colb));
        const float4 b1v = __ldg(reinterpret_cast<const float4*>(lin_b + colb + 4));
        const float bb[8] = {b0v.x, b0v.y, b0v.z, b0v.w, b1v.x, b1v.y, b1v.z, b1v.w};
#pragma unroll
        for (int mt = 0; mt < 2; mt++) {
            acc[mt][0][0] = bb[0]; acc[mt][0][1] = bb[1];
            acc[mt][1][0] = bb[2]; acc[mt][1][1] = bb[3];
            acc[mt][2][0] = bb[4]; acc[mt][2][1] = bb[5];
            acc[mt][3][0] = bb[6]; acc[mt][3][1] = bb[7];
            acc[mt][0][2] = bb[0]; acc[mt][0][3] = bb[1];
            acc[mt][1][2] = bb[2]; acc[mt][1][3] = bb[3];
            acc[mt][2][2] = bb[4]; acc[mt][2][3] = bb[5];
            acc[mt][3][2] = bb[6]; acc[mt][3][3] = bb[7];
        }
    }

    const int aoff0 = (32 * q + (lane & 15)) * LDA + ((lane >> 4) << 3);
    const uint32_t a_s0 = smem_u32(fhi + aoff0);
    const uint32_t a_s1 = smem_u32(fhi + aoff0 + 16 * LDA);
    const uint4* bp = g_bfrag + (G * 8) * 2 * 32 + lane;

#pragma unroll
    for (int c = 0; c < 8; c++) {
        const uint32_t kB = c * 32;
        uint32_t ah[2][4];
        LDSM_X4(ah[0][0], ah[0][1], ah[0][2], ah[0][3], a_s0 + kB);
        LDSM_X4(ah[1][0], ah[1][1], ah[1][2], ah[1][3], a_s1 + kB);
        const uint4 v0 = __ldg(bp + c * 64);
        const uint4 v1 = __ldg(bp + c * 64 + 32);
        const uint32_t bh[2][4] = {{v0.x, v0.y, v0.z, v0.w},
                                   {v1.x, v1.y, v1.z, v1.w}};
#pragma unroll
        for (int mt = 0; mt < 2; mt++) {
#pragma unroll
            for (int np = 0; np < 2; np++) {
                MMA16816(acc[mt][2*np+0], ah[mt][0], ah[mt][1], ah[mt][2], ah[mt][3],
                         bh[np][0], bh[np][1]);
                MMA16816(acc[mt][2*np+1], ah[mt][0], ah[mt][1], ah[mt][2], ah[mt][3],
                         bh[np][2], bh[np][3]);
            }
        }
    }

    // ---- epilogue: pure pack + streaming STG.128 (bias already in acc) ----
#pragma unroll
    for (int mt = 0; mt < 2; mt++) {
        const long row = s0 + 32 * q + mt * 16 + gid;
        float* ob = out + ((long)b * Sn + row) * Pn + colb;
        float4 r0a = make_float4(acc[mt][0][0], acc[mt][0][1],
                                 acc[mt][1][0], acc[mt][1][1]);
        float4 r0b = make_float4(acc[mt][2][0], acc[mt][2][1],
                                 acc[mt][3][0], acc[mt][3][1]);
        float4 r1a = make_float4(acc[mt][0][2], acc[mt][0][3],
                                 acc[mt][1][2], acc[mt][1][3]);
        float4 r1b = make_float4(acc[mt][2][2], acc[mt][2][3],
                                 acc[mt][3][2], acc[mt][3][3]);
        __stcs(reinterpret_cast<float4*>(ob),              r0a);
        __stcs(reinterpret_cast<float4*>(ob + 4),          r0b);
        __stcs(reinterpret_cast<float4*>(ob + 8 * Pn),     r1a);
        __stcs(reinterpret_cast<float4*>(ob + 8 * Pn + 4), r1b);
    }
}

extern "C" void kernel_launch(void* const* d_in, const int* in_sizes, int n_in,
                              void* d_out, int out_size) {
    (void)in_sizes; (void)n_in; (void)out_size;
    const float* x      = (const float*)d_in[0];
    const float* conv_w = (const float*)d_in[1];
    const float* conv_b = (const float*)d_in[2];
    const float* lin_w  = (const float*)d_in[3];
    const float* lin_b  = (const float*)d_in[4];
    float* out = (float*)d_out;

    pack_w_kernel<<<2, 256>>>(lin_w);

    cudaFuncSetAttribute(encoder_kernel,
                         cudaFuncAttributeMaxDynamicSharedMemorySize, SMEM_TOTAL);
    dim3 grid((unsigned)(Sn / S_TILE), Bn);
    encoder_kernel<<<grid, THREADS, SMEM_TOTAL>>>(x, conv_w, conv_b, lin_b, out);
}